// round 11
// baseline (speedup 1.0000x reference)
#include <cuda_runtime.h>
#include <cuda_fp16.h>
#include <cstdint>
#include <math.h>

#define E    1024
#define Dh   64
#define H    16
#define Ff   4096
#define Bb   2
#define Ss   2048
#define NT   (Bb*Ss)     // 4096 tokens
#define EPS  1e-5f

// ---------------- scratch (static device memory; no allocation) ----------------
__device__ __half g_h   [NT * E];        // LN1 output (fp16)
__device__ float  g_qkv [NT * 3 * E];    // fused q|k|v, row stride 3072 (fp32)
__device__ __half g_Wqkv[3 * E * E];     // packed W_qkv^T : [3072, 1024] (N,K) fp16
__device__ float  g_bqkv[3 * E];
__device__ __half g_WoT [E * E];         // Wo^T  fp16
__device__ __half g_W1T [Ff * E];        // W1^T  fp16
__device__ __half g_W2T [E * Ff];        // W2^T  fp16
__device__ __half g_o   [NT * E];        // attention out (fp16)
__device__ float  g_x1  [NT * E];        // after first residual (fp32)
__device__ __half g_h2  [NT * E];        // LN2 output (fp16)
__device__ __half g_m1  [NT * Ff];       // relu(h2 @ W1 + b1) (fp16)

// ======================= helpers =======================
__device__ __forceinline__ uint32_t smem_u32(const void* p) {
    uint32_t a;
    asm("{ .reg .u64 t; cvta.to.shared.u64 t, %1; cvt.u32.u64 %0, t; }" : "=r"(a) : "l"(p));
    return a;
}
__device__ __forceinline__ uint32_t f22h2(float a, float b) {
    __half2 h = __floats2half2_rn(a, b);
    return *(uint32_t*)&h;
}
#define CP_ASYNC16(dst, src) \
    asm volatile("cp.async.cg.shared.global [%0], [%1], 16;" :: "r"((uint32_t)(dst)), "l"(src))
#define CP_COMMIT() asm volatile("cp.async.commit_group;" ::: "memory")
#define CP_WAIT0()  asm volatile("cp.async.wait_group 0;" ::: "memory")
#define CP_WAIT1()  asm volatile("cp.async.wait_group 1;" ::: "memory")

#define LDMX4(r0, r1, r2, r3, addr) \
    asm volatile("ldmatrix.sync.aligned.m8n8.x4.shared.b16 {%0,%1,%2,%3}, [%4];" \
        : "=r"(r0), "=r"(r1), "=r"(r2), "=r"(r3) : "r"(addr))

// m16n8k16 fp16 mma: D(f32) += A(f16) * B(f16)
__device__ __forceinline__ void mma_f16(float* c, const uint32_t* a, uint32_t b0, uint32_t b1) {
    asm volatile(
        "mma.sync.aligned.m16n8k16.row.col.f32.f16.f16.f32 "
        "{%0,%1,%2,%3}, {%4,%5,%6,%7}, {%8,%9}, {%0,%1,%2,%3};"
        : "+f"(c[0]), "+f"(c[1]), "+f"(c[2]), "+f"(c[3])
        : "r"(a[0]), "r"(a[1]), "r"(a[2]), "r"(a[3]), "r"(b0), "r"(b1));
}

// ---------------- weight packing (fp16) ----------------
__global__ void pack_qkv_kernel(const float* __restrict__ Wq, const float* __restrict__ Wk,
                                const float* __restrict__ Wv, const float* __restrict__ bq,
                                const float* __restrict__ bk, const float* __restrict__ bv) {
    int i = blockIdx.x * blockDim.x + threadIdx.x;
    if (i < 3 * E * E) {
        int n = i >> 10;            // 0..3071
        int e = i & 1023;
        int wh = n >> 10;           // 0=q 1=k 2=v
        int hd = n & 1023;
        int h = hd >> 6, d = hd & 63;
        const float* W = (wh == 0) ? Wq : (wh == 1) ? Wk : Wv;
        g_Wqkv[i] = __float2half_rn(W[(h * E + e) * Dh + d]);
    }
    if (i < 3 * E) {
        const float* bs = (i < E) ? bq : (i < 2 * E) ? bk : bv;
        g_bqkv[i] = bs[i % E];
    }
}

// out[n*K + k] = fp16(in[k*N + n])
__global__ void transpose_kernel(const float* __restrict__ in, __half* __restrict__ out,
                                 int K, int N) {
    __shared__ float t[32][33];
    int k0 = blockIdx.x * 32, n0 = blockIdx.y * 32;
    int x = threadIdx.x, y = threadIdx.y;     // 32 x 8
    #pragma unroll
    for (int i = 0; i < 32; i += 8)
        t[y + i][x] = in[(size_t)(k0 + y + i) * N + n0 + x];
    __syncthreads();
    #pragma unroll
    for (int i = 0; i < 32; i += 8)
        out[(size_t)(n0 + y + i) * K + k0 + x] = __float2half_rn(t[x][y + i]);
}

// ---------------- layernorm (fp16 output) ----------------
__global__ void ln_kernel(const float* __restrict__ x, const float* __restrict__ g,
                          const float* __restrict__ b, __half* __restrict__ out) {
    int row = blockIdx.x;
    int tid = threadIdx.x;
    const float4 v = ((const float4*)(x + (size_t)row * E))[tid];
    float s  = v.x + v.y + v.z + v.w;
    float ss = v.x * v.x + v.y * v.y + v.z * v.z + v.w * v.w;
    #pragma unroll
    for (int o = 16; o; o >>= 1) {
        s  += __shfl_xor_sync(0xffffffffu, s,  o);
        ss += __shfl_xor_sync(0xffffffffu, ss, o);
    }
    __shared__ float sm[8], sm2[8];
    if ((tid & 31) == 0) { sm[tid >> 5] = s; sm2[tid >> 5] = ss; }
    __syncthreads();
    float tot = 0.f, tot2 = 0.f;
    #pragma unroll
    for (int i = 0; i < 8; i++) { tot += sm[i]; tot2 += sm2[i]; }
    float mean = tot * (1.0f / E);
    float var  = tot2 * (1.0f / E) - mean * mean;
    float inv  = rsqrtf(var + EPS);
    const float4 gg = ((const float4*)g)[tid];
    const float4 bb = ((const float4*)b)[tid];
    __half2* orow = (__half2*)(out + (size_t)row * E);
    orow[2 * tid]     = __floats2half2_rn((v.x - mean) * inv * gg.x + bb.x,
                                          (v.y - mean) * inv * gg.y + bb.y);
    orow[2 * tid + 1] = __floats2half2_rn((v.z - mean) * inv * gg.z + bb.z,
                                          (v.w - mean) * inv * gg.w + bb.w);
}

// ---------------- fp16 warp-MMA GEMM: C = A[M,K] @ Bt[N,K]^T (+bias)(+relu)(+res)
// CTA tile 128x128, 8 warps (32x64 each), K-chunk 64 halves, 3-stage cp.async.
// smem rows: 72 halves (144B = 9x16B) -> ldmatrix conflict-free.
#define LDH 72
#define TILE_H (128 * LDH * 2)          // 18432 bytes per tile
#define STAGE_H (2 * TILE_H)            // 36864
#define GEMMH_SMEM (3 * STAGE_H)        // 110592 -> 2 CTAs/SM

template<bool RELU, bool OUT_HALF>
__global__ __launch_bounds__(256, 2)
void gemm_h(const __half* __restrict__ A, const __half* __restrict__ Bt,
            const float* __restrict__ bias, const float* __restrict__ res,
            void* __restrict__ Cv, int M, int N, int K) {
    extern __shared__ char smem[];
    uint32_t sb = smem_u32(smem);
    int tid = threadIdx.x;
    int lane = tid & 31, wid = tid >> 5;
    int warp_m = wid & 3, warp_n = wid >> 2;        // 4 x 2 warp grid, warp 32x64
    int n0 = blockIdx.x * 128, m0 = blockIdx.y * 128;

    const __half* Abase = A  + (size_t)m0 * K;
    const __half* Bbase = Bt + (size_t)n0 * K;

    int NC = K >> 6;   // chunks of 64 halves

    // ldmatrix per-thread byte offsets (within a stage)
    int lt = lane >> 3, lr = lane & 7;
    uint32_t aoff[2], boff[4];
    #pragma unroll
    for (int mt = 0; mt < 2; mt++)
        aoff[mt] = ((warp_m * 32 + mt * 16 + (lt & 1) * 8 + lr) * 36 + (lt >> 1) * 4) * 4;
    #pragma unroll
    for (int nt2 = 0; nt2 < 4; nt2++)
        boff[nt2] = TILE_H + ((warp_n * 64 + nt2 * 16 + (lt & 1) * 8 + lr) * 36 + (lt >> 1) * 4) * 4;

    // prologue: chunks 0,1 -> stages 0,1
    #pragma unroll
    for (int st = 0; st < 2; st++) {
        uint32_t bufo = st * STAGE_H;
        int koff = st * 64;
        #pragma unroll
        for (int i = 0; i < 4; i++) {
            int idx = tid + i * 256;               // 1024 A slots
            int row = idx >> 3, seg = idx & 7;
            CP_ASYNC16(sb + bufo + row * 144 + seg * 16,
                       Abase + (size_t)row * K + koff + seg * 8);
        }
        #pragma unroll
        for (int i = 0; i < 4; i++) {
            int idx = tid + i * 256;               // 1024 B slots
            int row = idx >> 3, seg = idx & 7;
            CP_ASYNC16(sb + bufo + TILE_H + row * 144 + seg * 16,
                       Bbase + (size_t)row * K + koff + seg * 8);
        }
        CP_COMMIT();
    }
    CP_WAIT1();
    __syncthreads();

    float acc[2][8][4] = {};
    int cb = 0, pb = 2;

    int r = lane >> 2, cc = lane & 3;

    for (int c = 0; c < NC; c++) {
        if (c + 2 < NC) {
            uint32_t bufo = pb * STAGE_H;
            const __half* as = Abase + (c + 2) * 64;
            const __half* bs = Bbase + (c + 2) * 64;
            #pragma unroll
            for (int i = 0; i < 4; i++) {
                int idx = tid + i * 256;
                int row = idx >> 3, seg = idx & 7;
                CP_ASYNC16(sb + bufo + row * 144 + seg * 16,
                           as + (size_t)row * K + seg * 8);
            }
            #pragma unroll
            for (int i = 0; i < 4; i++) {
                int idx = tid + i * 256;
                int row = idx >> 3, seg = idx & 7;
                CP_ASYNC16(sb + bufo + TILE_H + row * 144 + seg * 16,
                           bs + (size_t)row * K + seg * 8);
            }
        }
        CP_COMMIT();

        uint32_t stage = sb + cb * STAGE_H;

        #pragma unroll
        for (int kk = 0; kk < 4; kk++) {           // 4 k16-steps
            uint32_t koff = kk * 32;               // 8 uint32 = 32 bytes
            uint32_t afr[2][4], bfr[4][4];
            LDMX4(afr[0][0], afr[0][1], afr[0][2], afr[0][3], stage + aoff[0] + koff);
            LDMX4(afr[1][0], afr[1][1], afr[1][2], afr[1][3], stage + aoff[1] + koff);
            #pragma unroll
            for (int nt2 = 0; nt2 < 4; nt2++)
                LDMX4(bfr[nt2][0], bfr[nt2][1], bfr[nt2][2], bfr[nt2][3], stage + boff[nt2] + koff);
            #pragma unroll
            for (int nt2 = 0; nt2 < 4; nt2++) {
                mma_f16(acc[0][2 * nt2    ], afr[0], bfr[nt2][0], bfr[nt2][2]);
                mma_f16(acc[1][2 * nt2    ], afr[1], bfr[nt2][0], bfr[nt2][2]);
                mma_f16(acc[0][2 * nt2 + 1], afr[0], bfr[nt2][1], bfr[nt2][3]);
                mma_f16(acc[1][2 * nt2 + 1], afr[1], bfr[nt2][1], bfr[nt2][3]);
            }
        }
        CP_WAIT1();
        __syncthreads();
        cb = (cb + 1 == 3) ? 0 : cb + 1;
        pb = (pb + 1 == 3) ? 0 : pb + 1;
    }

    // epilogue
    #pragma unroll
    for (int mt = 0; mt < 2; mt++) {
        #pragma unroll
        for (int nt = 0; nt < 8; nt++) {
            int col = n0 + warp_n * 64 + nt * 8 + cc * 2;
            float2 bv = *(const float2*)&bias[col];
            #pragma unroll
            for (int rr = 0; rr < 2; rr++) {
                int row = m0 + warp_m * 32 + mt * 16 + r + rr * 8;
                float vx = acc[mt][nt][rr * 2 + 0] + bv.x;
                float vy = acc[mt][nt][rr * 2 + 1] + bv.y;
                if (RELU) { vx = fmaxf(vx, 0.f); vy = fmaxf(vy, 0.f); }
                if (res) {
                    float2 rv = *(const float2*)&res[(size_t)row * N + col];
                    vx += rv.x; vy += rv.y;
                }
                if (OUT_HALF) {
                    *(uint32_t*)&((__half*)Cv)[(size_t)row * N + col] = f22h2(vx, vy);
                } else {
                    float2 v = { vx, vy };
                    *(float2*)&((float*)Cv)[(size_t)row * N + col] = v;
                }
            }
        }
    }
}

// ---------------- fp16 MMA flash attention (rows = keys, softmax over queries) --
// CTA: 128 key rows, 8 warps (m16 slab, K hi/lo fp16 frags in regs), t-tiles of 64.
// Q -> Qhi/Qlo half2 (cooperative), V -> Vh half2 transposed. P kept in registers.
// ldmatrix for all B-operand fragments.
#define QRAW_F 0
#define VRAW_F (64 * 68)
#define KF_F   (VRAW_F + 64 * 72)
#define VHU_OFF (KF_F + 128 * 36)
#define QHI_OFF (KF_F + 128 * 68)
#define QLO_OFF (QHI_OFF + 64 * 36)
#define ATT_SMEM ((QLO_OFF + 64 * 36) * 4)   // 89088 bytes

__global__ __launch_bounds__(256)
void attn_mma_kernel(const float* __restrict__ qkv, __half* __restrict__ o_out) {
    extern __shared__ float smf[];
    uint32_t sb = smem_u32(smf);
    uint32_t* smu = (uint32_t*)smf;

    int hb = blockIdx.y;
    int hh = hb >> 1, b = hb & 1;
    int s0 = blockIdx.x * 128;
    int tid = threadIdx.x, lane = tid & 31, wid = tid >> 5;
    int r = lane >> 2, cc = lane & 3;
    int rb = wid * 16 + r;

    // ldmatrix per-thread byte offsets (row index = t or d, stride 36 uint32)
    int lt = lane >> 3, lr = lane & 7;
    uint32_t qhio[4], qloo[4], voff[4];
    #pragma unroll
    for (int nt2 = 0; nt2 < 4; nt2++) {
        uint32_t ro = ((nt2 * 16 + (lt & 1) * 8 + lr) * 36 + (lt >> 1) * 4) * 4;
        qhio[nt2] = QHI_OFF * 4 + ro;
        qloo[nt2] = QLO_OFF * 4 + ro;
        voff[nt2] = VHU_OFF * 4 + ro;
    }

    const float* base = qkv + (size_t)(b * Ss) * 3072 + hh * 64;

    // K tile [128 x 64] fp32 (group 0)
    #pragma unroll
    for (int i = 0; i < 8; i++) {
        int idx = tid + i * 256;               // 0..2047
        int row = idx >> 4, seg = idx & 15;
        CP_ASYNC16(sb + (KF_F + row * 68) * 4 + seg * 16,
                   base + 1024 + (size_t)(s0 + row) * 3072 + seg * 4);
    }
    CP_COMMIT();
    // Q(0), V(0) (group 1)
    #pragma unroll
    for (int i = 0; i < 4; i++) {
        int idx = tid + i * 256;               // 0..1023
        int row = idx >> 4, seg = idx & 15;
        CP_ASYNC16(sb + (QRAW_F + row * 68) * 4 + seg * 16,
                   base + (size_t)row * 3072 + seg * 4);
        CP_ASYNC16(sb + (VRAW_F + row * 72) * 4 + seg * 16,
                   base + 2048 + (size_t)row * 3072 + seg * 4);
    }
    CP_COMMIT();
    CP_WAIT1();              // K resident
    __syncthreads();

    // K fragments hi/lo fp16 in registers: m16 x k64 (4 k16-steps)
    uint32_t kfh[4][4], kfl[4][4];
    #pragma unroll
    for (int kk = 0; kk < 4; kk++) {
        float2 kv[4];
        kv[0] = *(float2*)&smf[KF_F + (rb    ) * 68 + kk * 16 + 2 * cc];
        kv[1] = *(float2*)&smf[KF_F + (rb + 8) * 68 + kk * 16 + 2 * cc];
        kv[2] = *(float2*)&smf[KF_F + (rb    ) * 68 + kk * 16 + 2 * cc + 8];
        kv[3] = *(float2*)&smf[KF_F + (rb + 8) * 68 + kk * 16 + 2 * cc + 8];
        #pragma unroll
        for (int j = 0; j < 4; j++) {
            float hx = __half2float(__float2half_rn(kv[j].x));
            float hy = __half2float(__float2half_rn(kv[j].y));
            kfh[kk][j] = f22h2(hx, hy);
            kfl[kk][j] = f22h2(kv[j].x - hx, kv[j].y - hy);
        }
    }

    float mrow0 = -1e30f, mrow1 = -1e30f, lrow0 = 0.f, lrow1 = 0.f;
    float o[8][4] = {};

    int vd = (lane & 31) + 32 * (wid & 1);     // V-convert: this thread's d
    int vq = (vd >> 3) & 3;
    int vcb = (wid >> 1) * 8;

    for (int t0 = 0; t0 < Ss; t0 += 64) {
        CP_WAIT0();
        __syncthreads();       // Q(t)/V(t) resident; prior tile smem reads done

        // convert Q -> Qhi/Qlo (half2)
        #pragma unroll
        for (int i = 0; i < 8; i++) {
            int slot = tid + i * 256;          // 0..2047
            int t = slot >> 5, dp = slot & 31;
            float2 q = *(float2*)&smf[QRAW_F + t * 68 + 2 * dp];
            float hx = __half2float(__float2half_rn(q.x));
            float hy = __half2float(__float2half_rn(q.y));
            smu[QHI_OFF + t * 36 + dp] = f22h2(hx, hy);
            smu[QLO_OFF + t * 36 + dp] = f22h2(q.x - hx, q.y - hy);
        }
        // convert V -> Vh[d][t] (half2, transposed, xor-permuted write order)
        #pragma unroll
        for (int i = 0; i < 8; i++) {
            int tp = (vcb + i) ^ vq;
            float va = smf[VRAW_F + (2 * tp    ) * 72 + vd];
            float vb = smf[VRAW_F + (2 * tp + 1) * 72 + vd];
            smu[VHU_OFF + vd * 36 + tp] = f22h2(va, vb);
        }
        __syncthreads();

        if (t0 + 64 < Ss) {
            const float* src = base + (size_t)(t0 + 64) * 3072;
            #pragma unroll
            for (int i = 0; i < 4; i++) {
                int idx = tid + i * 256;
                int row = idx >> 4, seg = idx & 15;
                CP_ASYNC16(sb + (QRAW_F + row * 68) * 4 + seg * 16,
                           src + (size_t)row * 3072 + seg * 4);
                CP_ASYNC16(sb + (VRAW_F + row * 72) * 4 + seg * 16,
                           src + 2048 + (size_t)row * 3072 + seg * 4);
            }
            CP_COMMIT();
        }

        // S = K x Q^T : split-fp16 (3 MMAs per k16-step), B frags via ldmatrix
        float s[8][4] = {};
        #pragma unroll
        for (int kk = 0; kk < 4; kk++) {
            uint32_t koff = kk * 32;
            #pragma unroll
            for (int nt2 = 0; nt2 < 4; nt2++) {
                uint32_t qh[4], ql[4];
                LDMX4(qh[0], qh[1], qh[2], qh[3], sb + qhio[nt2] + koff);
                LDMX4(ql[0], ql[1], ql[2], ql[3], sb + qloo[nt2] + koff);
                mma_f16(s[2 * nt2    ], kfh[kk], qh[0], qh[2]);
                mma_f16(s[2 * nt2    ], kfh[kk], ql[0], ql[2]);
                mma_f16(s[2 * nt2    ], kfl[kk], qh[0], qh[2]);
                mma_f16(s[2 * nt2 + 1], kfh[kk], qh[1], qh[3]);
                mma_f16(s[2 * nt2 + 1], kfh[kk], ql[1], ql[3]);
                mma_f16(s[2 * nt2 + 1], kfl[kk], qh[1], qh[3]);
            }
        }

        // online softmax over t (rows in-warp: quad shfl reduce)
        float mx0 = -1e30f, mx1 = -1e30f;
        #pragma unroll
        for (int nt = 0; nt < 8; nt++) {
            mx0 = fmaxf(mx0, fmaxf(s[nt][0], s[nt][1]));
            mx1 = fmaxf(mx1, fmaxf(s[nt][2], s[nt][3]));
        }
        mx0 = fmaxf(mx0, __shfl_xor_sync(0xffffffffu, mx0, 1));
        mx0 = fmaxf(mx0, __shfl_xor_sync(0xffffffffu, mx0, 2));
        mx1 = fmaxf(mx1, __shfl_xor_sync(0xffffffffu, mx1, 1));
        mx1 = fmaxf(mx1, __shfl_xor_sync(0xffffffffu, mx1, 2));
        float mn0 = fmaxf(mrow0, mx0), mn1 = fmaxf(mrow1, mx1);
        float a0 = __expf(mrow0 - mn0), a1 = __expf(mrow1 - mn1);
        mrow0 = mn0; mrow1 = mn1;

        // P in registers (half2), accumulator layout == A-fragment layout
        uint32_t pp0[8], pp1[8];
        float ps0 = 0.f, ps1 = 0.f;
        #pragma unroll
        for (int nt = 0; nt < 8; nt++) {
            float p0 = __expf(s[nt][0] - mn0);
            float p1 = __expf(s[nt][1] - mn0);
            float p2 = __expf(s[nt][2] - mn1);
            float p3 = __expf(s[nt][3] - mn1);
            ps0 += p0 + p1;
            ps1 += p2 + p3;
            pp0[nt] = f22h2(p0, p1);
            pp1[nt] = f22h2(p2, p3);
        }
        ps0 += __shfl_xor_sync(0xffffffffu, ps0, 1);
        ps0 += __shfl_xor_sync(0xffffffffu, ps0, 2);
        ps1 += __shfl_xor_sync(0xffffffffu, ps1, 1);
        ps1 += __shfl_xor_sync(0xffffffffu, ps1, 2);
        lrow0 = lrow0 * a0 + ps0;
        lrow1 = lrow1 * a1 + ps1;
        #pragma unroll
        for (int nt = 0; nt < 8; nt++) {
            o[nt][0] *= a0; o[nt][1] *= a0;
            o[nt][2] *= a1; o[nt][3] *= a1;
        }

        // O += P x V (P from regs, V frags via ldmatrix)
        #pragma unroll
        for (int kk = 0; kk < 4; kk++) {
            uint32_t koff = kk * 32;
            uint32_t pa[4] = { pp0[2 * kk], pp1[2 * kk], pp0[2 * kk + 1], pp1[2 * kk + 1] };
            #pragma unroll
            for (int nt2 = 0; nt2 < 4; nt2++) {
                uint32_t vf[4];
                LDMX4(vf[0], vf[1], vf[2], vf[3], sb + voff[nt2] + koff);
                mma_f16(o[2 * nt2    ], pa, vf[0], vf[2]);
                mma_f16(o[2 * nt2 + 1], pa, vf[1], vf[3]);
            }
        }
    }

    float i0 = 1.f / lrow0, i1 = 1.f / lrow1;
    uint32_t* orow0 = (uint32_t*)(o_out + (size_t)(b * Ss + s0 + rb) * E + hh * 64);
    uint32_t* orow1 = (uint32_t*)(o_out + (size_t)(b * Ss + s0 + rb + 8) * E + hh * 64);
    #pragma unroll
    for (int nt = 0; nt < 8; nt++) {
        orow0[nt * 4 + cc] = f22h2(o[nt][0] * i0, o[nt][1] * i0);
        orow1[nt * 4 + cc] = f22h2(o[nt][2] * i1, o[nt][3] * i1);
    }
}

// ---------------- host launch ----------------
extern "C" void kernel_launch(void* const* d_in, const int* in_sizes, int n_in,
                              void* d_out, int out_size) {
    const float* x     = (const float*)d_in[0];
    const float* Wq    = (const float*)d_in[1];
    const float* bq    = (const float*)d_in[2];
    const float* Wk    = (const float*)d_in[3];
    const float* bk    = (const float*)d_in[4];
    const float* Wv    = (const float*)d_in[5];
    const float* bv    = (const float*)d_in[6];
    const float* Wo    = (const float*)d_in[7];
    const float* bo    = (const float*)d_in[8];
    const float* ln1_g = (const float*)d_in[9];
    const float* ln1_b = (const float*)d_in[10];
    const float* ln2_g = (const float*)d_in[11];
    const float* ln2_b = (const float*)d_in[12];
    const float* W1    = (const float*)d_in[13];
    const float* b1    = (const float*)d_in[14];
    const float* W2    = (const float*)d_in[15];
    const float* b2    = (const float*)d_in[16];
    float* out = (float*)d_out;

    __half *p_h, *p_Wqkv, *p_WoT, *p_W1T, *p_W2T, *p_o, *p_h2, *p_m1;
    float *p_qkv, *p_bqkv, *p_x1;
    cudaGetSymbolAddress((void**)&p_h,    g_h);
    cudaGetSymbolAddress((void**)&p_qkv,  g_qkv);
    cudaGetSymbolAddress((void**)&p_Wqkv, g_Wqkv);
    cudaGetSymbolAddress((void**)&p_bqkv, g_bqkv);
    cudaGetSymbolAddress((void**)&p_WoT,  g_WoT);
    cudaGetSymbolAddress((void**)&p_W1T,  g_W1T);
    cudaGetSymbolAddress((void**)&p_W2T,  g_W2T);
    cudaGetSymbolAddress((void**)&p_o,    g_o);
    cudaGetSymbolAddress((void**)&p_x1,   g_x1);
    cudaGetSymbolAddress((void**)&p_h2,   g_h2);
    cudaGetSymbolAddress((void**)&p_m1,   g_m1);

    cudaFuncSetAttribute(gemm_h<false, false>, cudaFuncAttributeMaxDynamicSharedMemorySize, GEMMH_SMEM);
    cudaFuncSetAttribute(gemm_h<true,  true>,  cudaFuncAttributeMaxDynamicSharedMemorySize, GEMMH_SMEM);
    cudaFuncSetAttribute(attn_mma_kernel,      cudaFuncAttributeMaxDynamicSharedMemorySize, ATT_SMEM);

    // 1. pack fused QKV weight (transposed, fp16) + bias; transpose Wo, W1, W2 (fp16)
    pack_qkv_kernel<<<(3 * E * E + 255) / 256, 256>>>(Wq, Wk, Wv, bq, bk, bv);
    transpose_kernel<<<dim3(E / 32, E / 32),  dim3(32, 8)>>>(Wo, p_WoT, E, E);
    transpose_kernel<<<dim3(E / 32, Ff / 32), dim3(32, 8)>>>(W1, p_W1T, E, Ff);
    transpose_kernel<<<dim3(Ff / 32, E / 32), dim3(32, 8)>>>(W2, p_W2T, Ff, E);

    // 2. LN1 (fp16 out)
    ln_kernel<<<NT, 256>>>(x, ln1_g, ln1_b, p_h);

    // 3. fused QKV projection: [4096,1024] @ [1024,3072]  (fp32 out -> split-fp16 attn)
    gemm_h<false, false><<<dim3(3 * E / 128, NT / 128), 256, GEMMH_SMEM>>>(p_h, p_Wqkv, p_bqkv, nullptr, p_qkv, NT, 3 * E, E);

    // 4. attention (split-fp16 S, fp16 PV) -> fp16 o
    attn_mma_kernel<<<dim3(Ss / 128, H * Bb), 256, ATT_SMEM>>>(p_qkv, p_o);

    // 5. output projection + residual (fp32 out)
    gemm_h<false, false><<<dim3(E / 128, NT / 128), 256, GEMMH_SMEM>>>(p_o, p_WoT, bo, x, p_x1, NT, E, E);

    // 6. LN2 (fp16 out)
    ln_kernel<<<NT, 256>>>(p_x1, ln2_g, ln2_b, p_h2);

    // 7. MLP up + ReLU (fp16 out -> feeds MLP down as A)
    gemm_h<true, true><<<dim3(Ff / 128, NT / 128), 256, GEMMH_SMEM>>>(p_h2, p_W1T, b1, nullptr, p_m1, NT, Ff, E);

    // 8. MLP down + residual -> fp32 output
    gemm_h<false, false><<<dim3(E / 128, NT / 128), 256, GEMMH_SMEM>>>(p_m1, p_W2T, b2, p_x1, out, NT, E, Ff);
}

// round 12
// speedup vs baseline: 1.7279x; 1.7279x over previous
#include <cuda_runtime.h>
#include <cuda_fp16.h>
#include <cstdint>
#include <math.h>

#define E    1024
#define Dh   64
#define H    16
#define Ff   4096
#define Bb   2
#define Ss   2048
#define NT   (Bb*Ss)     // 4096 tokens
#define EPS  1e-5f

// ---------------- scratch (static device memory; no allocation) ----------------
__device__ __half g_h   [NT * E];        // LN1 output (fp16)
__device__ float  g_qkv [NT * 3 * E];    // fused q|k|v, row stride 3072 (fp32)
__device__ __half g_Wqkv[3 * E * E];     // packed W_qkv^T : [3072, 1024] (N,K) fp16
__device__ float  g_bqkv[3 * E];
__device__ __half g_WoT [E * E];         // Wo^T  fp16
__device__ __half g_W1T [Ff * E];        // W1^T  fp16
__device__ __half g_W2T [E * Ff];        // W2^T  fp16
__device__ __half g_o   [NT * E];        // attention out (fp16)
__device__ float  g_x1  [NT * E];        // after first residual (fp32)
__device__ __half g_h2  [NT * E];        // LN2 output (fp16)
__device__ __half g_m1  [NT * Ff];       // relu(h2 @ W1 + b1) (fp16)

// ======================= helpers =======================
__device__ __forceinline__ uint32_t smem_u32(const void* p) {
    uint32_t a;
    asm("{ .reg .u64 t; cvta.to.shared.u64 t, %1; cvt.u32.u64 %0, t; }" : "=r"(a) : "l"(p));
    return a;
}
__device__ __forceinline__ uint32_t f22h2(float a, float b) {
    __half2 h = __floats2half2_rn(a, b);
    return *(uint32_t*)&h;
}
#define CP_ASYNC16(dst, src) \
    asm volatile("cp.async.cg.shared.global [%0], [%1], 16;" :: "r"((uint32_t)(dst)), "l"(src))
#define CP_COMMIT() asm volatile("cp.async.commit_group;" ::: "memory")
#define CP_WAIT0()  asm volatile("cp.async.wait_group 0;" ::: "memory")
#define CP_WAIT1()  asm volatile("cp.async.wait_group 1;" ::: "memory")

#define LDMX4(r0, r1, r2, r3, addr) \
    asm volatile("ldmatrix.sync.aligned.m8n8.x4.shared.b16 {%0,%1,%2,%3}, [%4];" \
        : "=r"(r0), "=r"(r1), "=r"(r2), "=r"(r3) : "r"(addr))

// m16n8k16 fp16 mma: D(f32) += A(f16) * B(f16)
__device__ __forceinline__ void mma_f16(float* c, const uint32_t* a, uint32_t b0, uint32_t b1) {
    asm volatile(
        "mma.sync.aligned.m16n8k16.row.col.f32.f16.f16.f32 "
        "{%0,%1,%2,%3}, {%4,%5,%6,%7}, {%8,%9}, {%0,%1,%2,%3};"
        : "+f"(c[0]), "+f"(c[1]), "+f"(c[2]), "+f"(c[3])
        : "r"(a[0]), "r"(a[1]), "r"(a[2]), "r"(a[3]), "r"(b0), "r"(b1));
}

// ---------------- weight packing (fp16) ----------------
__global__ void pack_qkv_kernel(const float* __restrict__ Wq, const float* __restrict__ Wk,
                                const float* __restrict__ Wv, const float* __restrict__ bq,
                                const float* __restrict__ bk, const float* __restrict__ bv) {
    int i = blockIdx.x * blockDim.x + threadIdx.x;
    if (i < 3 * E * E) {
        int n = i >> 10;            // 0..3071
        int e = i & 1023;
        int wh = n >> 10;           // 0=q 1=k 2=v
        int hd = n & 1023;
        int h = hd >> 6, d = hd & 63;
        const float* W = (wh == 0) ? Wq : (wh == 1) ? Wk : Wv;
        g_Wqkv[i] = __float2half_rn(W[(h * E + e) * Dh + d]);
    }
    if (i < 3 * E) {
        const float* bs = (i < E) ? bq : (i < 2 * E) ? bk : bv;
        g_bqkv[i] = bs[i % E];
    }
}

// out[n*K + k] = fp16(in[k*N + n])
__global__ void transpose_kernel(const float* __restrict__ in, __half* __restrict__ out,
                                 int K, int N) {
    __shared__ float t[32][33];
    int k0 = blockIdx.x * 32, n0 = blockIdx.y * 32;
    int x = threadIdx.x, y = threadIdx.y;     // 32 x 8
    #pragma unroll
    for (int i = 0; i < 32; i += 8)
        t[y + i][x] = in[(size_t)(k0 + y + i) * N + n0 + x];
    __syncthreads();
    #pragma unroll
    for (int i = 0; i < 32; i += 8)
        out[(size_t)(n0 + y + i) * K + k0 + x] = __float2half_rn(t[x][y + i]);
}

// ---------------- layernorm (fp16 output) ----------------
__global__ void ln_kernel(const float* __restrict__ x, const float* __restrict__ g,
                          const float* __restrict__ b, __half* __restrict__ out) {
    int row = blockIdx.x;
    int tid = threadIdx.x;
    const float4 v = ((const float4*)(x + (size_t)row * E))[tid];
    float s  = v.x + v.y + v.z + v.w;
    float ss = v.x * v.x + v.y * v.y + v.z * v.z + v.w * v.w;
    #pragma unroll
    for (int o = 16; o; o >>= 1) {
        s  += __shfl_xor_sync(0xffffffffu, s,  o);
        ss += __shfl_xor_sync(0xffffffffu, ss, o);
    }
    __shared__ float sm[8], sm2[8];
    if ((tid & 31) == 0) { sm[tid >> 5] = s; sm2[tid >> 5] = ss; }
    __syncthreads();
    float tot = 0.f, tot2 = 0.f;
    #pragma unroll
    for (int i = 0; i < 8; i++) { tot += sm[i]; tot2 += sm2[i]; }
    float mean = tot * (1.0f / E);
    float var  = tot2 * (1.0f / E) - mean * mean;
    float inv  = rsqrtf(var + EPS);
    const float4 gg = ((const float4*)g)[tid];
    const float4 bb = ((const float4*)b)[tid];
    __half2* orow = (__half2*)(out + (size_t)row * E);
    orow[2 * tid]     = __floats2half2_rn((v.x - mean) * inv * gg.x + bb.x,
                                          (v.y - mean) * inv * gg.y + bb.y);
    orow[2 * tid + 1] = __floats2half2_rn((v.z - mean) * inv * gg.z + bb.z,
                                          (v.w - mean) * inv * gg.w + bb.w);
}

// ---------------- fp16 warp-MMA GEMM: C = A[M,K] @ Bt[N,K]^T (+bias)(+relu)(+res)
// CTA tile 128x128, 8 warps (32x64 each), K-chunk 64 halves, 3-stage cp.async.
// ldmatrix.x4 fragment loads; B loaded just-in-time to cap register liveness.
#define LDH 72
#define TILE_H (128 * LDH * 2)          // 18432 bytes per tile
#define STAGE_H (2 * TILE_H)            // 36864
#define GEMMH_SMEM (3 * STAGE_H)        // 110592 -> 2 CTAs/SM

template<bool RELU, bool OUT_HALF>
__global__ __launch_bounds__(256, 2)
void gemm_h(const __half* __restrict__ A, const __half* __restrict__ Bt,
            const float* __restrict__ bias, const float* __restrict__ res,
            void* __restrict__ Cv, int M, int N, int K) {
    extern __shared__ char smem[];
    uint32_t sb = smem_u32(smem);
    int tid = threadIdx.x;
    int lane = tid & 31, wid = tid >> 5;
    int warp_m = wid & 3, warp_n = wid >> 2;        // 4 x 2 warp grid, warp 32x64
    int n0 = blockIdx.x * 128, m0 = blockIdx.y * 128;

    const __half* Abase = A  + (size_t)m0 * K;
    const __half* Bbase = Bt + (size_t)n0 * K;

    int NC = K >> 6;   // chunks of 64 halves

    // ldmatrix per-thread byte offsets (within a stage)
    int lt = lane >> 3, lr = lane & 7;
    uint32_t aoff[2], boff[4];
    #pragma unroll
    for (int mt = 0; mt < 2; mt++)
        aoff[mt] = ((warp_m * 32 + mt * 16 + (lt & 1) * 8 + lr) * 36 + (lt >> 1) * 4) * 4;
    #pragma unroll
    for (int nt2 = 0; nt2 < 4; nt2++)
        boff[nt2] = TILE_H + ((warp_n * 64 + nt2 * 16 + (lt & 1) * 8 + lr) * 36 + (lt >> 1) * 4) * 4;

    // prologue: chunks 0,1 -> stages 0,1
    #pragma unroll
    for (int st = 0; st < 2; st++) {
        uint32_t bufo = st * STAGE_H;
        int koff = st * 64;
        #pragma unroll
        for (int i = 0; i < 4; i++) {
            int idx = tid + i * 256;               // 1024 A slots
            int row = idx >> 3, seg = idx & 7;
            CP_ASYNC16(sb + bufo + row * 144 + seg * 16,
                       Abase + (size_t)row * K + koff + seg * 8);
        }
        #pragma unroll
        for (int i = 0; i < 4; i++) {
            int idx = tid + i * 256;               // 1024 B slots
            int row = idx >> 3, seg = idx & 7;
            CP_ASYNC16(sb + bufo + TILE_H + row * 144 + seg * 16,
                       Bbase + (size_t)row * K + koff + seg * 8);
        }
        CP_COMMIT();
    }
    CP_WAIT1();
    __syncthreads();

    float acc[2][8][4] = {};
    int cb = 0, pb = 2;

    int r = lane >> 2, cc = lane & 3;

    for (int c = 0; c < NC; c++) {
        if (c + 2 < NC) {
            uint32_t bufo = pb * STAGE_H;
            const __half* as = Abase + (c + 2) * 64;
            const __half* bs = Bbase + (c + 2) * 64;
            #pragma unroll
            for (int i = 0; i < 4; i++) {
                int idx = tid + i * 256;
                int row = idx >> 3, seg = idx & 7;
                CP_ASYNC16(sb + bufo + row * 144 + seg * 16,
                           as + (size_t)row * K + seg * 8);
            }
            #pragma unroll
            for (int i = 0; i < 4; i++) {
                int idx = tid + i * 256;
                int row = idx >> 3, seg = idx & 7;
                CP_ASYNC16(sb + bufo + TILE_H + row * 144 + seg * 16,
                           bs + (size_t)row * K + seg * 8);
            }
        }
        CP_COMMIT();

        uint32_t stage = sb + cb * STAGE_H;

        #pragma unroll
        for (int kk = 0; kk < 4; kk++) {           // 4 k16-steps
            uint32_t koff = kk * 32;               // 8 uint32 = 32 bytes
            uint32_t afr[2][4];
            LDMX4(afr[0][0], afr[0][1], afr[0][2], afr[0][3], stage + aoff[0] + koff);
            LDMX4(afr[1][0], afr[1][1], afr[1][2], afr[1][3], stage + aoff[1] + koff);
            #pragma unroll
            for (int nt2 = 0; nt2 < 4; nt2++) {
                uint32_t bfr[4];                   // just-in-time B frags (4 live regs)
                LDMX4(bfr[0], bfr[1], bfr[2], bfr[3], stage + boff[nt2] + koff);
                mma_f16(acc[0][2 * nt2    ], afr[0], bfr[0], bfr[2]);
                mma_f16(acc[1][2 * nt2    ], afr[1], bfr[0], bfr[2]);
                mma_f16(acc[0][2 * nt2 + 1], afr[0], bfr[1], bfr[3]);
                mma_f16(acc[1][2 * nt2 + 1], afr[1], bfr[1], bfr[3]);
            }
        }
        CP_WAIT1();
        __syncthreads();
        cb = (cb + 1 == 3) ? 0 : cb + 1;
        pb = (pb + 1 == 3) ? 0 : pb + 1;
    }

    // epilogue
    #pragma unroll
    for (int mt = 0; mt < 2; mt++) {
        #pragma unroll
        for (int nt = 0; nt < 8; nt++) {
            int col = n0 + warp_n * 64 + nt * 8 + cc * 2;
            float2 bv = *(const float2*)&bias[col];
            #pragma unroll
            for (int rr = 0; rr < 2; rr++) {
                int row = m0 + warp_m * 32 + mt * 16 + r + rr * 8;
                float vx = acc[mt][nt][rr * 2 + 0] + bv.x;
                float vy = acc[mt][nt][rr * 2 + 1] + bv.y;
                if (RELU) { vx = fmaxf(vx, 0.f); vy = fmaxf(vy, 0.f); }
                if (res) {
                    float2 rv = *(const float2*)&res[(size_t)row * N + col];
                    vx += rv.x; vy += rv.y;
                }
                if (OUT_HALF) {
                    *(uint32_t*)&((__half*)Cv)[(size_t)row * N + col] = f22h2(vx, vy);
                } else {
                    float2 v = { vx, vy };
                    *(float2*)&((float*)Cv)[(size_t)row * N + col] = v;
                }
            }
        }
    }
}

// ---------------- fp16 MMA flash attention (R10 version, known-good) -----------
// CTA: 128 key rows, 8 warps (m16 slab, K hi/lo fp16 frags in regs), t-tiles of 64.
#define QRAW_F 0
#define VRAW_F (64 * 68)
#define KF_F   (VRAW_F + 64 * 72)
#define PU_OFF (KF_F)                    // uint index == float index
#define VHU_OFF (KF_F + 128 * 36)
#define QHI_OFF (KF_F + 128 * 68)
#define QLO_OFF (QHI_OFF + 64 * 36)
#define ATT_SMEM ((QLO_OFF + 64 * 36) * 4)   // 89088 bytes

__global__ __launch_bounds__(256)
void attn_mma_kernel(const float* __restrict__ qkv, __half* __restrict__ o_out) {
    extern __shared__ float smf[];
    uint32_t sb = smem_u32(smf);
    uint32_t* smu = (uint32_t*)smf;

    int hb = blockIdx.y;
    int hh = hb >> 1, b = hb & 1;
    int s0 = blockIdx.x * 128;
    int tid = threadIdx.x, lane = tid & 31, wid = tid >> 5;
    int r = lane >> 2, cc = lane & 3;
    int rb = wid * 16 + r;

    const float* base = qkv + (size_t)(b * Ss) * 3072 + hh * 64;

    // K tile [128 x 64] fp32 (group 0)
    #pragma unroll
    for (int i = 0; i < 8; i++) {
        int idx = tid + i * 256;               // 0..2047
        int row = idx >> 4, seg = idx & 15;
        CP_ASYNC16(sb + (KF_F + row * 68) * 4 + seg * 16,
                   base + 1024 + (size_t)(s0 + row) * 3072 + seg * 4);
    }
    CP_COMMIT();
    // Q(0), V(0) (group 1)
    #pragma unroll
    for (int i = 0; i < 4; i++) {
        int idx = tid + i * 256;               // 0..1023
        int row = idx >> 4, seg = idx & 15;
        CP_ASYNC16(sb + (QRAW_F + row * 68) * 4 + seg * 16,
                   base + (size_t)row * 3072 + seg * 4);
        CP_ASYNC16(sb + (VRAW_F + row * 72) * 4 + seg * 16,
                   base + 2048 + (size_t)row * 3072 + seg * 4);
    }
    CP_COMMIT();
    CP_WAIT1();              // K resident
    __syncthreads();

    // K fragments hi/lo fp16 in registers: m16 x k64 (4 k16-steps)
    uint32_t kfh[4][4], kfl[4][4];
    #pragma unroll
    for (int kk = 0; kk < 4; kk++) {
        float2 kv[4];
        kv[0] = *(float2*)&smf[KF_F + (rb    ) * 68 + kk * 16 + 2 * cc];
        kv[1] = *(float2*)&smf[KF_F + (rb + 8) * 68 + kk * 16 + 2 * cc];
        kv[2] = *(float2*)&smf[KF_F + (rb    ) * 68 + kk * 16 + 2 * cc + 8];
        kv[3] = *(float2*)&smf[KF_F + (rb + 8) * 68 + kk * 16 + 2 * cc + 8];
        #pragma unroll
        for (int j = 0; j < 4; j++) {
            float hx = __half2float(__float2half_rn(kv[j].x));
            float hy = __half2float(__float2half_rn(kv[j].y));
            kfh[kk][j] = f22h2(hx, hy);
            kfl[kk][j] = f22h2(kv[j].x - hx, kv[j].y - hy);
        }
    }

    float mrow0 = -1e30f, mrow1 = -1e30f, lrow0 = 0.f, lrow1 = 0.f;
    float o[8][4] = {};

    int vd = (lane & 31) + 32 * (wid & 1);     // V-convert: this thread's d
    int vq = (vd >> 3) & 3;
    int vcb = (wid >> 1) * 8;

    for (int t0 = 0; t0 < Ss; t0 += 64) {
        CP_WAIT0();
        __syncthreads();       // Q(t)/V(t) resident; prior tile smem reads done

        // convert Q -> Qhi/Qlo (half2)
        #pragma unroll
        for (int i = 0; i < 8; i++) {
            int slot = tid + i * 256;          // 0..2047
            int t = slot >> 5, dp = slot & 31;
            float2 q = *(float2*)&smf[QRAW_F + t * 68 + 2 * dp];
            float hx = __half2float(__float2half_rn(q.x));
            float hy = __half2float(__float2half_rn(q.y));
            smu[QHI_OFF + t * 36 + dp] = f22h2(hx, hy);
            smu[QLO_OFF + t * 36 + dp] = f22h2(q.x - hx, q.y - hy);
        }
        // convert V -> Vh[d][t] (half2, transposed, xor-permuted write order)
        #pragma unroll
        for (int i = 0; i < 8; i++) {
            int tp = (vcb + i) ^ vq;
            float va = smf[VRAW_F + (2 * tp    ) * 72 + vd];
            float vb = smf[VRAW_F + (2 * tp + 1) * 72 + vd];
            smu[VHU_OFF + vd * 36 + tp] = f22h2(va, vb);
        }
        __syncthreads();

        if (t0 + 64 < Ss) {
            const float* src = base + (size_t)(t0 + 64) * 3072;
            #pragma unroll
            for (int i = 0; i < 4; i++) {
                int idx = tid + i * 256;
                int row = idx >> 4, seg = idx & 15;
                CP_ASYNC16(sb + (QRAW_F + row * 68) * 4 + seg * 16,
                           src + (size_t)row * 3072 + seg * 4);
                CP_ASYNC16(sb + (VRAW_F + row * 72) * 4 + seg * 16,
                           src + 2048 + (size_t)row * 3072 + seg * 4);
            }
            CP_COMMIT();
        }

        // S = K x Q^T : split-fp16 (3 MMAs per k16-step)
        float s[8][4] = {};
        #pragma unroll
        for (int kk = 0; kk < 4; kk++) {
            int ko = kk * 8;
            #pragma unroll
            for (int nt = 0; nt < 8; nt++) {
                int qr = (nt * 8 + r) * 36 + ko + cc;
                uint32_t b0h = smu[QHI_OFF + qr];
                uint32_t b1h = smu[QHI_OFF + qr + 4];
                uint32_t b0l = smu[QLO_OFF + qr];
                uint32_t b1l = smu[QLO_OFF + qr + 4];
                mma_f16(s[nt], kfh[kk], b0h, b1h);
                mma_f16(s[nt], kfh[kk], b0l, b1l);
                mma_f16(s[nt], kfl[kk], b0h, b1h);
            }
        }

        // online softmax over t (rows in-warp: quad shfl reduce)
        float mx0 = -1e30f, mx1 = -1e30f;
        #pragma unroll
        for (int nt = 0; nt < 8; nt++) {
            mx0 = fmaxf(mx0, fmaxf(s[nt][0], s[nt][1]));
            mx1 = fmaxf(mx1, fmaxf(s[nt][2], s[nt][3]));
        }
        mx0 = fmaxf(mx0, __shfl_xor_sync(0xffffffffu, mx0, 1));
        mx0 = fmaxf(mx0, __shfl_xor_sync(0xffffffffu, mx0, 2));
        mx1 = fmaxf(mx1, __shfl_xor_sync(0xffffffffu, mx1, 1));
        mx1 = fmaxf(mx1, __shfl_xor_sync(0xffffffffu, mx1, 2));
        float mn0 = fmaxf(mrow0, mx0), mn1 = fmaxf(mrow1, mx1);
        float a0 = __expf(mrow0 - mn0), a1 = __expf(mrow1 - mn1);
        mrow0 = mn0; mrow1 = mn1;

        float ps0 = 0.f, ps1 = 0.f;
        #pragma unroll
        for (int nt = 0; nt < 8; nt++) {
            float p0 = __expf(s[nt][0] - mn0);
            float p1 = __expf(s[nt][1] - mn0);
            float p2 = __expf(s[nt][2] - mn1);
            float p3 = __expf(s[nt][3] - mn1);
            ps0 += p0 + p1;
            ps1 += p2 + p3;
            smu[PU_OFF + (rb    ) * 36 + nt * 4 + cc] = f22h2(p0, p1);
            smu[PU_OFF + (rb + 8) * 36 + nt * 4 + cc] = f22h2(p2, p3);
        }
        ps0 += __shfl_xor_sync(0xffffffffu, ps0, 1);
        ps0 += __shfl_xor_sync(0xffffffffu, ps0, 2);
        ps1 += __shfl_xor_sync(0xffffffffu, ps1, 1);
        ps1 += __shfl_xor_sync(0xffffffffu, ps1, 2);
        lrow0 = lrow0 * a0 + ps0;
        lrow1 = lrow1 * a1 + ps1;
        #pragma unroll
        for (int nt = 0; nt < 8; nt++) {
            o[nt][0] *= a0; o[nt][1] *= a0;
            o[nt][2] *= a1; o[nt][3] *= a1;
        }
        __syncwarp();   // this warp's P rows visible (warp-private rows)

        // O += P x V (fp16)
        #pragma unroll
        for (int kk = 0; kk < 4; kk++) {
            int ko = kk * 8;
            uint32_t pa[4];
            pa[0] = smu[PU_OFF + (rb    ) * 36 + ko + cc];
            pa[1] = smu[PU_OFF + (rb + 8) * 36 + ko + cc];
            pa[2] = smu[PU_OFF + (rb    ) * 36 + ko + cc + 4];
            pa[3] = smu[PU_OFF + (rb + 8) * 36 + ko + cc + 4];
            #pragma unroll
            for (int nt = 0; nt < 8; nt++) {
                uint32_t b0 = smu[VHU_OFF + (nt * 8 + r) * 36 + ko + cc];
                uint32_t b1 = smu[VHU_OFF + (nt * 8 + r) * 36 + ko + cc + 4];
                mma_f16(o[nt], pa, b0, b1);
            }
        }
    }

    float i0 = 1.f / lrow0, i1 = 1.f / lrow1;
    uint32_t* orow0 = (uint32_t*)(o_out + (size_t)(b * Ss + s0 + rb) * E + hh * 64);
    uint32_t* orow1 = (uint32_t*)(o_out + (size_t)(b * Ss + s0 + rb + 8) * E + hh * 64);
    #pragma unroll
    for (int nt = 0; nt < 8; nt++) {
        orow0[nt * 4 + cc] = f22h2(o[nt][0] * i0, o[nt][1] * i0);
        orow1[nt * 4 + cc] = f22h2(o[nt][2] * i1, o[nt][3] * i1);
    }
}

// ---------------- host launch ----------------
extern "C" void kernel_launch(void* const* d_in, const int* in_sizes, int n_in,
                              void* d_out, int out_size) {
    const float* x     = (const float*)d_in[0];
    const float* Wq    = (const float*)d_in[1];
    const float* bq    = (const float*)d_in[2];
    const float* Wk    = (const float*)d_in[3];
    const float* bk    = (const float*)d_in[4];
    const float* Wv    = (const float*)d_in[5];
    const float* bv    = (const float*)d_in[6];
    const float* Wo    = (const float*)d_in[7];
    const float* bo    = (const float*)d_in[8];
    const float* ln1_g = (const float*)d_in[9];
    const float* ln1_b = (const float*)d_in[10];
    const float* ln2_g = (const float*)d_in[11];
    const float* ln2_b = (const float*)d_in[12];
    const float* W1    = (const float*)d_in[13];
    const float* b1    = (const float*)d_in[14];
    const float* W2    = (const float*)d_in[15];
    const float* b2    = (const float*)d_in[16];
    float* out = (float*)d_out;

    __half *p_h, *p_Wqkv, *p_WoT, *p_W1T, *p_W2T, *p_o, *p_h2, *p_m1;
    float *p_qkv, *p_bqkv, *p_x1;
    cudaGetSymbolAddress((void**)&p_h,    g_h);
    cudaGetSymbolAddress((void**)&p_qkv,  g_qkv);
    cudaGetSymbolAddress((void**)&p_Wqkv, g_Wqkv);
    cudaGetSymbolAddress((void**)&p_bqkv, g_bqkv);
    cudaGetSymbolAddress((void**)&p_WoT,  g_WoT);
    cudaGetSymbolAddress((void**)&p_W1T,  g_W1T);
    cudaGetSymbolAddress((void**)&p_W2T,  g_W2T);
    cudaGetSymbolAddress((void**)&p_o,    g_o);
    cudaGetSymbolAddress((void**)&p_x1,   g_x1);
    cudaGetSymbolAddress((void**)&p_h2,   g_h2);
    cudaGetSymbolAddress((void**)&p_m1,   g_m1);

    cudaFuncSetAttribute(gemm_h<false, false>, cudaFuncAttributeMaxDynamicSharedMemorySize, GEMMH_SMEM);
    cudaFuncSetAttribute(gemm_h<true,  true>,  cudaFuncAttributeMaxDynamicSharedMemorySize, GEMMH_SMEM);
    cudaFuncSetAttribute(attn_mma_kernel,      cudaFuncAttributeMaxDynamicSharedMemorySize, ATT_SMEM);

    // 1. pack fused QKV weight (transposed, fp16) + bias; transpose Wo, W1, W2 (fp16)
    pack_qkv_kernel<<<(3 * E * E + 255) / 256, 256>>>(Wq, Wk, Wv, bq, bk, bv);
    transpose_kernel<<<dim3(E / 32, E / 32),  dim3(32, 8)>>>(Wo, p_WoT, E, E);
    transpose_kernel<<<dim3(E / 32, Ff / 32), dim3(32, 8)>>>(W1, p_W1T, E, Ff);
    transpose_kernel<<<dim3(Ff / 32, E / 32), dim3(32, 8)>>>(W2, p_W2T, Ff, E);

    // 2. LN1 (fp16 out)
    ln_kernel<<<NT, 256>>>(x, ln1_g, ln1_b, p_h);

    // 3. fused QKV projection: [4096,1024] @ [1024,3072]  (fp32 out -> split-fp16 attn)
    gemm_h<false, false><<<dim3(3 * E / 128, NT / 128), 256, GEMMH_SMEM>>>(p_h, p_Wqkv, p_bqkv, nullptr, p_qkv, NT, 3 * E, E);

    // 4. attention (split-fp16 S, fp16 PV) -> fp16 o
    attn_mma_kernel<<<dim3(Ss / 128, H * Bb), 256, ATT_SMEM>>>(p_qkv, p_o);

    // 5. output projection + residual (fp32 out)
    gemm_h<false, false><<<dim3(E / 128, NT / 128), 256, GEMMH_SMEM>>>(p_o, p_WoT, bo, x, p_x1, NT, E, E);

    // 6. LN2 (fp16 out)
    ln_kernel<<<NT, 256>>>(p_x1, ln2_g, ln2_b, p_h2);

    // 7. MLP up + ReLU (fp16 out -> feeds MLP down as A)
    gemm_h<true, true><<<dim3(Ff / 128, NT / 128), 256, GEMMH_SMEM>>>(p_h2, p_W1T, b1, nullptr, p_m1, NT, Ff, E);

    // 8. MLP down + residual -> fp32 output
    gemm_h<false, false><<<dim3(E / 128, NT / 128), 256, GEMMH_SMEM>>>(p_m1, p_W2T, b2, p_x1, out, NT, E, Ff);
}